// round 1
// baseline (speedup 1.0000x reference)
#include <cuda_runtime.h>

#define H        128   // hidden size / output cols of W1
#define K2       256   // 2*H concat feature dim
#define ET       64    // edges per tile
#define NTHREADS 256

// ---- packed f32x2 helpers (sm_103a) ----
__device__ __forceinline__ unsigned long long pack2(float a, float b) {
    unsigned long long r;
    asm("mov.b64 %0, {%1, %2};" : "=l"(r) : "r"(__float_as_uint(a)), "r"(__float_as_uint(b)));
    return r;
}
__device__ __forceinline__ void unpack2(unsigned long long v, float& a, float& b) {
    unsigned int lo, hi;
    asm("mov.b64 {%0, %1}, %2;" : "=r"(lo), "=r"(hi) : "l"(v));
    a = __uint_as_float(lo);
    b = __uint_as_float(hi);
}
__device__ __forceinline__ unsigned long long fma2(unsigned long long a,
                                                   unsigned long long b,
                                                   unsigned long long c) {
    unsigned long long d;
    asm("fma.rn.f32x2 %0, %1, %2, %3;" : "=l"(d) : "l"(a), "l"(b), "l"(c));
    return d;
}

// smem layout (floats): sW1[K2*H] | sZ[ET*K2] | sW2[H] | sB1[H] | sRow[ET](int) | sCol[ET](int)
#define SMEM_BYTES ((K2*H + ET*K2 + H + H) * 4 + ET * 4 * 2)

__global__ void __launch_bounds__(NTHREADS, 1)
edge_decoder_kernel(const float* __restrict__ zs,   // [N_STUDENT, H]
                    const float* __restrict__ zc,   // [N_COURSE, H]
                    const int*   __restrict__ row,  // [E]
                    const int*   __restrict__ col,  // [E]
                    const float* __restrict__ W1,   // [K2, H] row-major
                    const float* __restrict__ b1,   // [H]
                    const float* __restrict__ W2,   // [H]
                    const float* __restrict__ b2,   // [1]
                    float* __restrict__ out,        // [E]
                    int E)
{
    extern __shared__ float sm[];
    float* sW1 = sm;                  // K2*H
    float* sZ  = sW1 + K2 * H;        // ET*K2
    float* sW2 = sZ + ET * K2;        // H
    float* sB1 = sW2 + H;             // H
    int*   sRow = (int*)(sB1 + H);    // ET
    int*   sCol = sRow + ET;          // ET

    const int tid  = threadIdx.x;
    const int lane = tid & 31;
    const int warp = tid >> 5;
    const int c0   = lane * 4;        // 4 output columns per lane
    const int e0   = warp * 8;        // 8 edges per warp

    // ---- stage W1 / W2 / b1 once per CTA ----
    {
        const float4* W1v = (const float4*)W1;
        float4* sW1v = (float4*)sW1;
        #pragma unroll
        for (int i = 0; i < (K2 * H / 4) / NTHREADS; i++)
            sW1v[tid + i * NTHREADS] = W1v[tid + i * NTHREADS];
        if (tid < H) { sW2[tid] = W2[tid]; sB1[tid] = b1[tid]; }
    }
    __syncthreads();

    float w2r[4], b1r[4];
    #pragma unroll
    for (int c = 0; c < 4; c++) { w2r[c] = sW2[c0 + c]; b1r[c] = sB1[c0 + c]; }
    const float bias2 = b2[0];

    const int numTiles = (E + ET - 1) / ET;
    for (int tile = blockIdx.x; tile < numTiles; tile += gridDim.x) {
        const int base = tile * ET;

        // ---- stage indices ----
        if (tid < ET) {
            int e = base + tid;
            if (e < E) { sRow[tid] = row[e]; sCol[tid] = col[e]; }
            else       { sRow[tid] = 0;      sCol[tid] = 0; }
        }
        __syncthreads();

        // ---- gather 64 edges x 256 floats into smem (coalesced float4) ----
        {
            float4* sZv = (float4*)sZ;
            #pragma unroll
            for (int i = 0; i < (ET * K2 / 4) / NTHREADS; i++) {  // 16 iters
                int idx = tid + i * NTHREADS;
                int e = idx >> 6;      // 64 float4 per edge
                int f = idx & 63;
                const float* src = (f < 32)
                    ? (zs + (size_t)sRow[e] * H + (f << 2))
                    : (zc + (size_t)sCol[e] * H + ((f - 32) << 2));
                sZv[idx] = *(const float4*)src;
            }
        }
        __syncthreads();

        // ---- layer 1: acc[pair][col] over k=0..255, packed f32x2 over edge pairs ----
        unsigned long long acc[4][4];
        #pragma unroll
        for (int p = 0; p < 4; p++)
            #pragma unroll
            for (int c = 0; c < 4; c++)
                acc[p][c] = 0ull;   // bits of (0.0f, 0.0f)

        #pragma unroll 4
        for (int k = 0; k < K2; k++) {
            float4 wv = *(const float4*)(sW1 + k * H + c0);
            unsigned long long w2p[4];
            w2p[0] = pack2(wv.x, wv.x);
            w2p[1] = pack2(wv.y, wv.y);
            w2p[2] = pack2(wv.z, wv.z);
            w2p[3] = pack2(wv.w, wv.w);
            #pragma unroll
            for (int p = 0; p < 4; p++) {
                float za = sZ[(e0 + 2 * p)     * K2 + k];
                float zb = sZ[(e0 + 2 * p + 1) * K2 + k];
                unsigned long long zp = pack2(za, zb);
                acc[p][0] = fma2(zp, w2p[0], acc[p][0]);
                acc[p][1] = fma2(zp, w2p[1], acc[p][1]);
                acc[p][2] = fma2(zp, w2p[2], acc[p][2]);
                acc[p][3] = fma2(zp, w2p[3], acc[p][3]);
            }
        }

        // ---- bias + ReLU + layer 2 partial, then butterfly-reduce over lanes (c dim) ----
        float s[8];
        #pragma unroll
        for (int p = 0; p < 4; p++) {
            float pa = 0.f, pb = 0.f;
            #pragma unroll
            for (int c = 0; c < 4; c++) {
                float ha, hb;
                unpack2(acc[p][c], ha, hb);
                ha = fmaxf(ha + b1r[c], 0.f);
                hb = fmaxf(hb + b1r[c], 0.f);
                pa += ha * w2r[c];
                pb += hb * w2r[c];
            }
            #pragma unroll
            for (int m = 16; m > 0; m >>= 1) {
                pa += __shfl_xor_sync(0xffffffffu, pa, m);
                pb += __shfl_xor_sync(0xffffffffu, pb, m);
            }
            s[2 * p]     = pa;
            s[2 * p + 1] = pb;
        }

        if (lane == 0) {
            int eg = base + e0;
            if (eg + 7 < E) {
                float4 v0 = make_float4(s[0] + bias2, s[1] + bias2, s[2] + bias2, s[3] + bias2);
                float4 v1 = make_float4(s[4] + bias2, s[5] + bias2, s[6] + bias2, s[7] + bias2);
                *(float4*)(out + eg)     = v0;
                *(float4*)(out + eg + 4) = v1;
            } else {
                #pragma unroll
                for (int j = 0; j < 8; j++)
                    if (eg + j < E) out[eg + j] = s[j] + bias2;
            }
        }
        __syncthreads();   // protect sRow/sZ before next iteration's writes
    }
}

extern "C" void kernel_launch(void* const* d_in, const int* in_sizes, int n_in,
                              void* d_out, int out_size)
{
    const float* zs  = (const float*)d_in[0];
    const float* zc  = (const float*)d_in[1];
    const int*   row = (const int*)d_in[2];   // jax default downcasts int64 -> int32
    const int*   col = (const int*)d_in[3];
    const float* W1  = (const float*)d_in[4];
    const float* b1  = (const float*)d_in[5];
    const float* W2  = (const float*)d_in[6];
    const float* b2  = (const float*)d_in[7];
    float* out = (float*)d_out;
    const int E = in_sizes[2];

    static bool attr_set = false;  // idempotent attribute set (not a work guard)
    if (!attr_set) {
        cudaFuncSetAttribute(edge_decoder_kernel,
                             cudaFuncAttributeMaxDynamicSharedMemorySize, SMEM_BYTES);
        attr_set = true;
    }

    int sms = 148;
    cudaDeviceGetAttribute(&sms, cudaDevAttrMultiProcessorCount, 0);

    edge_decoder_kernel<<<sms, NTHREADS, SMEM_BYTES>>>(
        zs, zc, row, col, W1, b1, W2, b2, out, E);
}

// round 3
// speedup vs baseline: 2.5695x; 2.5695x over previous
#include <cuda_runtime.h>
#include <cstdint>

#define NT     256
#define ETILE  32
#define KDIM   256
#define HID    128
#define SROW   528                     // bytes per edge-row per precision (16B-aligned, bank-spread)
#define ZPREC  (ETILE * SROW)          // 16896 B
#define LOOFF  ZPREC                   // lo plane offset inside a buffer
#define ZBUF   (2 * ZPREC)             // hi+lo per buffer = 33792 B
#define OFF_PRT 0                      // 8 warps * 32 edges * 4B = 1024
#define OFF_Z   1024
#define SMEM_BYTES (OFF_Z + 2 * ZBUF)  // 68608 B

// ---------------- helpers ----------------
__device__ __forceinline__ uint32_t smem_u32(const void* p) {
    uint32_t a;
    asm("{ .reg .u64 t; cvta.to.shared.u64 t, %1; cvt.u32.u64 %0, t; }" : "=r"(a) : "l"(p));
    return a;
}
// pack (lo, hi) floats into bf16x2 register, lo in bits[0:16]
__device__ __forceinline__ uint32_t bfpair(float lo, float hi) {
    uint32_t r;
    asm("cvt.rn.bf16x2.f32 %0, %1, %2;" : "=r"(r) : "f"(hi), "f"(lo));
    return r;
}
__device__ __forceinline__ float bf_lo(uint32_t p) { return __uint_as_float(p << 16); }
__device__ __forceinline__ float bf_hi(uint32_t p) { return __uint_as_float(p & 0xffff0000u); }

__device__ __forceinline__ void ldmat4(uint32_t (&r)[4], uint32_t addr) {
    asm volatile("ldmatrix.sync.aligned.m8n8.x4.shared.b16 {%0,%1,%2,%3}, [%4];"
                 : "=r"(r[0]), "=r"(r[1]), "=r"(r[2]), "=r"(r[3]) : "r"(addr));
}
__device__ __forceinline__ void mma16816(float (&d)[4], const uint32_t (&a)[4],
                                         uint32_t b0, uint32_t b1) {
    asm volatile("mma.sync.aligned.m16n8k16.row.col.f32.bf16.bf16.f32 "
                 "{%0,%1,%2,%3}, {%4,%5,%6,%7}, {%8,%9}, {%0,%1,%2,%3};"
                 : "+f"(d[0]), "+f"(d[1]), "+f"(d[2]), "+f"(d[3])
                 : "r"(a[0]), "r"(a[1]), "r"(a[2]), "r"(a[3]), "r"(b0), "r"(b1));
}

// ---------------- gather: gmem prefetch + convert/store ----------------
__device__ __forceinline__ void pref_load(const float* __restrict__ zs,
                                          const float* __restrict__ zc,
                                          const int* __restrict__ row,
                                          const int* __restrict__ col,
                                          int base, int E, int tid, float4 (&v)[8]) {
    const int e = tid >> 3, seg = tid & 7;
    const int eg = base + e;
    const float* src;
    if (seg < 4) {
        int idx = (eg < E) ? row[eg] : 0;
        src = zs + (size_t)idx * HID + seg * 32;
    } else {
        int idx = (eg < E) ? col[eg] : 0;
        src = zc + (size_t)idx * HID + (seg - 4) * 32;
    }
    #pragma unroll
    for (int j = 0; j < 8; j++) v[j] = ((const float4*)src)[j];
}

__device__ __forceinline__ void pref_store(char* zbuf, int tid, const float4 (&v)[8]) {
    const int e = tid >> 3, seg = tid & 7;
    char* hb = zbuf + e * SROW + seg * 64;
    #pragma unroll
    for (int i = 0; i < 4; i++) {
        float f0 = v[2*i].x, f1 = v[2*i].y, f2 = v[2*i].z, f3 = v[2*i].w;
        float f4 = v[2*i+1].x, f5 = v[2*i+1].y, f6 = v[2*i+1].z, f7 = v[2*i+1].w;
        uint32_t h0 = bfpair(f0, f1), h1 = bfpair(f2, f3);
        uint32_t h2 = bfpair(f4, f5), h3 = bfpair(f6, f7);
        uint32_t l0 = bfpair(f0 - bf_lo(h0), f1 - bf_hi(h0));
        uint32_t l1 = bfpair(f2 - bf_lo(h1), f3 - bf_hi(h1));
        uint32_t l2 = bfpair(f4 - bf_lo(h2), f5 - bf_hi(h2));
        uint32_t l3 = bfpair(f6 - bf_lo(h3), f7 - bf_hi(h3));
        *(uint4*)(hb + i * 16)         = make_uint4(h0, h1, h2, h3);
        *(uint4*)(hb + LOOFF + i * 16) = make_uint4(l0, l1, l2, l3);
    }
}

// ---------------- kernel ----------------
__global__ void __launch_bounds__(NT, 1)
edge_decoder_mma(const float* __restrict__ zs, const float* __restrict__ zc,
                 const int* __restrict__ row, const int* __restrict__ col,
                 const float* __restrict__ W1, const float* __restrict__ b1,
                 const float* __restrict__ W2, const float* __restrict__ b2,
                 float* __restrict__ out, int E)
{
    extern __shared__ __align__(16) char sm[];
    float* prt = (float*)(sm + OFF_PRT);
    char*  zsm = sm + OFF_Z;

    const int tid  = threadIdx.x;
    const int lane = tid & 31;
    const int wid  = tid >> 5;
    const int tq   = lane & 3;    // quad id -> column pair within n8
    const int tr   = lane >> 2;   // row within m16
    const int wcol = wid * 16;    // this warp's 16 output columns

    // ---- B = W1 fragments, bf16 hi/lo, register-resident (constant all run) ----
    // b0 covers k = s*16 + 2*tq (+1); b1 covers k+8. n = wcol + nb*8 + tr.
    uint32_t Bh[2][16][2], Bl[2][16][2];
    #pragma unroll
    for (int nb = 0; nb < 2; nb++) {
        const int n = wcol + nb * 8 + tr;
        #pragma unroll
        for (int s = 0; s < 16; s++) {
            #pragma unroll
            for (int h = 0; h < 2; h++) {
                const int k0 = s * 16 + tq * 2 + h * 8;
                float w0 = W1[(size_t)k0 * HID + n];
                float w1 = W1[(size_t)(k0 + 1) * HID + n];
                uint32_t hp = bfpair(w0, w1);
                Bh[nb][s][h] = hp;
                Bl[nb][s][h] = bfpair(w0 - bf_lo(hp), w1 - bf_hi(hp));
            }
        }
    }

    // ---- epilogue constants: this thread's 4 columns (nb,j) ----
    float b1v[2][2], w2v[2][2];
    #pragma unroll
    for (int nb = 0; nb < 2; nb++)
        #pragma unroll
        for (int j = 0; j < 2; j++) {
            int c = wcol + nb * 8 + tq * 2 + j;
            b1v[nb][j] = b1[c];
            w2v[nb][j] = W2[c];
        }
    const float b2v = b2[0];

    // per-lane ldmatrix base: lanes 0-15 -> rows 0-15 (k byte 0), 16-31 -> rows, k byte +16
    const uint32_t zb0 = smem_u32(zsm);
    const uint32_t lanebase = (uint32_t)(lane & 15) * SROW + (uint32_t)(lane >> 4) * 16;

    const int numTiles = (E + ETILE - 1) / ETILE;
    int t = blockIdx.x;
    int buf = 0;
    float4 pv[8];

    if (t < numTiles) {
        pref_load(zs, zc, row, col, t * ETILE, E, tid, pv);
        pref_store(zsm, tid, pv);
    }

    while (t < numTiles) {
        const int tn = t + gridDim.x;
        __syncthreads();   // current buf STS visible to all; prt free

        // issue next tile's gmem loads now -> latency hidden under MMA
        if (tn < numTiles) pref_load(zs, zc, row, col, tn * ETILE, E, tid, pv);

        // ---- MMA mainloop over K, 3 passes (hh, hl, lh) ----
        float D[2][2][4];
        #pragma unroll
        for (int mb = 0; mb < 2; mb++)
            #pragma unroll
            for (int nb = 0; nb < 2; nb++)
                #pragma unroll
                for (int i = 0; i < 4; i++) D[mb][nb][i] = 0.f;

        const uint32_t zb = zb0 + (uint32_t)buf * ZBUF;
        #pragma unroll
        for (int s = 0; s < 16; s++) {
            uint32_t Ah[2][4], Al[2][4];
            #pragma unroll
            for (int mb = 0; mb < 2; mb++) {
                uint32_t ad = zb + lanebase + (uint32_t)mb * (16 * SROW) + (uint32_t)s * 32;
                ldmat4(Ah[mb], ad);
                ldmat4(Al[mb], ad + LOOFF);
            }
            #pragma unroll
            for (int mb = 0; mb < 2; mb++)
                #pragma unroll
                for (int nb = 0; nb < 2; nb++) {
                    mma16816(D[mb][nb], Ah[mb], Bh[nb][s][0], Bh[nb][s][1]);
                    mma16816(D[mb][nb], Ah[mb], Bl[nb][s][0], Bl[nb][s][1]);
                    mma16816(D[mb][nb], Al[mb], Bh[nb][s][0], Bh[nb][s][1]);
                }
        }

        // convert + store next tile into other buffer (overlaps nothing reading it)
        if (tn < numTiles) pref_store(zsm + (buf ^ 1) * ZBUF, tid, pv);

        // ---- epilogue: bias + ReLU + W2, reduce cols ----
        #pragma unroll
        for (int mb = 0; mb < 2; mb++) {
            float s0 = 0.f, s1 = 0.f;
            #pragma unroll
            for (int nb = 0; nb < 2; nb++) {
                s0 += fmaxf(D[mb][nb][0] + b1v[nb][0], 0.f) * w2v[nb][0];
                s0 += fmaxf(D[mb][nb][1] + b1v[nb][1], 0.f) * w2v[nb][1];
                s1 += fmaxf(D[mb][nb][2] + b1v[nb][0], 0.f) * w2v[nb][0];
                s1 += fmaxf(D[mb][nb][3] + b1v[nb][1], 0.f) * w2v[nb][1];
            }
            s0 += __shfl_xor_sync(0xffffffffu, s0, 1);
            s0 += __shfl_xor_sync(0xffffffffu, s0, 2);
            s1 += __shfl_xor_sync(0xffffffffu, s1, 1);
            s1 += __shfl_xor_sync(0xffffffffu, s1, 2);
            if (tq == 0) {
                prt[wid * 32 + mb * 16 + tr]     = s0;   // edge = mb*16 + tr
                prt[wid * 32 + mb * 16 + tr + 8] = s1;   // edge = mb*16 + tr + 8
            }
        }
        __syncthreads();
        if (tid < ETILE) {
            float o = b2v;
            #pragma unroll
            for (int w = 0; w < 8; w++) o += prt[w * 32 + tid];
            int eg = t * ETILE + tid;
            if (eg < E) out[eg] = o;
        }

        t = tn;
        buf ^= 1;
    }
}

extern "C" void kernel_launch(void* const* d_in, const int* in_sizes, int n_in,
                              void* d_out, int out_size)
{
    const float* zs  = (const float*)d_in[0];
    const float* zc  = (const float*)d_in[1];
    const int*   row = (const int*)d_in[2];
    const int*   col = (const int*)d_in[3];
    const float* W1  = (const float*)d_in[4];
    const float* b1  = (const float*)d_in[5];
    const float* W2  = (const float*)d_in[6];
    const float* b2  = (const float*)d_in[7];
    float* out = (float*)d_out;
    const int E = in_sizes[2];

    static bool attr_set = false;  // idempotent, not a work guard
    if (!attr_set) {
        cudaFuncSetAttribute(edge_decoder_mma,
                             cudaFuncAttributeMaxDynamicSharedMemorySize, SMEM_BYTES);
        attr_set = true;
    }

    int sms = 148;
    cudaDeviceGetAttribute(&sms, cudaDevAttrMultiProcessorCount, 0);
    int numTiles = (E + ETILE - 1) / ETILE;
    int grid = sms < numTiles ? sms : numTiles;

    edge_decoder_mma<<<grid, NT, SMEM_BYTES>>>(zs, zc, row, col, W1, b1, W2, b2, out, E);
}

// round 4
// speedup vs baseline: 4.7214x; 1.8375x over previous
#include <cuda_runtime.h>
#include <cstdint>

#define NT     256
#define ETILE  32
#define KDIM   256
#define HID    128
#define SROW   528                     // bytes per edge-row (256 fp16 + 16B pad)
#define ZBUF   (ETILE * SROW)          // 16896 B per buffer
#define OFF_PRT 0                      // 8 warps * 32 floats = 1KB
#define OFF_Z   1024
#define SMEM_BYTES (OFF_Z + 2 * ZBUF)  // 34816 B -> 2 CTAs/SM

// ---------------- helpers ----------------
__device__ __forceinline__ uint32_t smem_u32(const void* p) {
    uint32_t a;
    asm("{ .reg .u64 t; cvta.to.shared.u64 t, %1; cvt.u32.u64 %0, t; }" : "=r"(a) : "l"(p));
    return a;
}
// pack (lo, hi) floats into f16x2 register, lo in bits[0:16]
__device__ __forceinline__ uint32_t hfpair(float lo, float hi) {
    uint32_t r;
    asm("cvt.rn.f16x2.f32 %0, %1, %2;" : "=r"(r) : "f"(hi), "f"(lo));
    return r;
}
__device__ __forceinline__ void ldmat4(uint32_t (&r)[4], uint32_t addr) {
    asm volatile("ldmatrix.sync.aligned.m8n8.x4.shared.b16 {%0,%1,%2,%3}, [%4];"
                 : "=r"(r[0]), "=r"(r[1]), "=r"(r[2]), "=r"(r[3]) : "r"(addr));
}
__device__ __forceinline__ void mma16816(float (&d)[4], const uint32_t (&a)[4],
                                         uint32_t b0, uint32_t b1) {
    asm volatile("mma.sync.aligned.m16n8k16.row.col.f32.f16.f16.f32 "
                 "{%0,%1,%2,%3}, {%4,%5,%6,%7}, {%8,%9}, {%0,%1,%2,%3};"
                 : "+f"(d[0]), "+f"(d[1]), "+f"(d[2]), "+f"(d[3])
                 : "r"(a[0]), "r"(a[1]), "r"(a[2]), "r"(a[3]), "r"(b0), "r"(b1));
}

// ---------------- gather: gmem load + fp16 convert (regs) ----------------
__device__ __forceinline__ void pref_load(const float* __restrict__ zs,
                                          const float* __restrict__ zc,
                                          const int* __restrict__ row,
                                          const int* __restrict__ col,
                                          int base, int E, int tid, uint32_t (&h)[16]) {
    const int e = tid >> 3, seg = tid & 7;   // 32 edges x 8 segs of 32 floats
    const int eg = base + e;
    const float* src;
    if (seg < 4) {
        int idx = (eg < E) ? row[eg] : 0;
        src = zs + (size_t)idx * HID + seg * 32;
    } else {
        int idx = (eg < E) ? col[eg] : 0;
        src = zc + (size_t)idx * HID + (seg - 4) * 32;
    }
    #pragma unroll
    for (int j = 0; j < 8; j++) {
        float4 v = ((const float4*)src)[j];
        h[2 * j]     = hfpair(v.x, v.y);
        h[2 * j + 1] = hfpair(v.z, v.w);
    }
}
__device__ __forceinline__ void pref_store(char* zbuf, int tid, const uint32_t (&h)[16]) {
    const int e = tid >> 3, seg = tid & 7;
    char* hb = zbuf + e * SROW + seg * 64;   // 32 halfs = 64B per thread
    #pragma unroll
    for (int i = 0; i < 4; i++)
        *(uint4*)(hb + i * 16) = make_uint4(h[4*i], h[4*i+1], h[4*i+2], h[4*i+3]);
}

// ---------------- kernel ----------------
__global__ void __launch_bounds__(NT, 2)
edge_decoder_mma(const float* __restrict__ zs, const float* __restrict__ zc,
                 const int* __restrict__ row, const int* __restrict__ col,
                 const float* __restrict__ W1, const float* __restrict__ b1,
                 const float* __restrict__ W2, const float* __restrict__ b2,
                 float* __restrict__ out, int E)
{
    extern __shared__ __align__(16) char sm[];
    float* prt = (float*)(sm + OFF_PRT);
    char*  zsm = sm + OFF_Z;

    const int tid  = threadIdx.x;
    const int lane = tid & 31;
    const int wid  = tid >> 5;
    const int tq   = lane & 3;    // quad -> column pair within n8
    const int tr   = lane >> 2;   // row within m16 / col within n8
    const int wcol = wid * 16;    // this warp's 16 output columns

    // ---- B = W1 fragments, fp16, register-resident ----
    // b0 covers k = s*16 + 2*tq (+1); b1 covers k+8. n = wcol + nb*8 + tr.
    uint32_t B[2][16][2];
    #pragma unroll
    for (int nb = 0; nb < 2; nb++) {
        const int n = wcol + nb * 8 + tr;
        #pragma unroll
        for (int s = 0; s < 16; s++) {
            #pragma unroll
            for (int hh = 0; hh < 2; hh++) {
                const int k0 = s * 16 + tq * 2 + hh * 8;
                B[nb][s][hh] = hfpair(W1[(size_t)k0 * HID + n],
                                      W1[(size_t)(k0 + 1) * HID + n]);
            }
        }
    }

    // ---- epilogue constants: this thread's 4 columns (nb,j) ----
    float b1v[2][2], w2v[2][2];
    #pragma unroll
    for (int nb = 0; nb < 2; nb++)
        #pragma unroll
        for (int j = 0; j < 2; j++) {
            int c = wcol + nb * 8 + tq * 2 + j;
            b1v[nb][j] = b1[c];
            w2v[nb][j] = W2[c];
        }
    const float b2v = b2[0];

    const uint32_t zb0 = smem_u32(zsm);
    const uint32_t lanebase = (uint32_t)(lane & 15) * SROW + (uint32_t)(lane >> 4) * 16;

    const int numTiles = (E + ETILE - 1) / ETILE;
    int t = blockIdx.x;
    int buf = 0;
    uint32_t pv[16];

    if (t < numTiles) {
        pref_load(zs, zc, row, col, t * ETILE, E, tid, pv);
        pref_store(zsm, tid, pv);
    }

    while (t < numTiles) {
        const int tn = t + gridDim.x;
        __syncthreads();   // buf visible; prt free

        // issue next tile's gmem loads now -> latency hidden under MMA
        if (tn < numTiles) pref_load(zs, zc, row, col, tn * ETILE, E, tid, pv);

        // ---- MMA mainloop, single fp16 pass ----
        float D[2][2][4];
        #pragma unroll
        for (int mb = 0; mb < 2; mb++)
            #pragma unroll
            for (int nb = 0; nb < 2; nb++)
                #pragma unroll
                for (int i = 0; i < 4; i++) D[mb][nb][i] = 0.f;

        const uint32_t zb = zb0 + (uint32_t)buf * ZBUF;
        #pragma unroll
        for (int s = 0; s < 16; s++) {
            uint32_t A[2][4];
            #pragma unroll
            for (int mb = 0; mb < 2; mb++)
                ldmat4(A[mb], zb + lanebase + (uint32_t)mb * (16 * SROW) + (uint32_t)s * 32);
            #pragma unroll
            for (int mb = 0; mb < 2; mb++)
                #pragma unroll
                for (int nb = 0; nb < 2; nb++)
                    mma16816(D[mb][nb], A[mb], B[nb][s][0], B[nb][s][1]);
        }

        // convert + store next tile into other buffer
        if (tn < numTiles) pref_store(zsm + (buf ^ 1) * ZBUF, tid, pv);

        // ---- epilogue: bias + ReLU + W2, reduce ----
        #pragma unroll
        for (int mb = 0; mb < 2; mb++) {
            float s0 = 0.f, s1 = 0.f;
            #pragma unroll
            for (int nb = 0; nb < 2; nb++) {
                s0 += fmaxf(D[mb][nb][0] + b1v[nb][0], 0.f) * w2v[nb][0];
                s0 += fmaxf(D[mb][nb][1] + b1v[nb][1], 0.f) * w2v[nb][1];
                s1 += fmaxf(D[mb][nb][2] + b1v[nb][0], 0.f) * w2v[nb][0];
                s1 += fmaxf(D[mb][nb][3] + b1v[nb][1], 0.f) * w2v[nb][1];
            }
            s0 += __shfl_xor_sync(0xffffffffu, s0, 1);
            s0 += __shfl_xor_sync(0xffffffffu, s0, 2);
            s1 += __shfl_xor_sync(0xffffffffu, s1, 1);
            s1 += __shfl_xor_sync(0xffffffffu, s1, 2);
            if (tq == 0) {
                prt[wid * 32 + mb * 16 + tr]     = s0;   // edge = mb*16 + tr
                prt[wid * 32 + mb * 16 + tr + 8] = s1;   // edge = mb*16 + tr + 8
            }
        }
        __syncthreads();
        if (tid < ETILE) {
            float o = b2v;
            #pragma unroll
            for (int w = 0; w < 8; w++) o += prt[w * 32 + tid];
            int eg = t * ETILE + tid;
            if (eg < E) out[eg] = o;
        }

        t = tn;
        buf ^= 1;
    }
}

extern "C" void kernel_launch(void* const* d_in, const int* in_sizes, int n_in,
                              void* d_out, int out_size)
{
    const float* zs  = (const float*)d_in[0];
    const float* zc  = (const float*)d_in[1];
    const int*   row = (const int*)d_in[2];
    const int*   col = (const int*)d_in[3];
    const float* W1  = (const float*)d_in[4];
    const float* b1  = (const float*)d_in[5];
    const float* W2  = (const float*)d_in[6];
    const float* b2  = (const float*)d_in[7];
    float* out = (float*)d_out;
    const int E = in_sizes[2];

    static bool attr_set = false;  // idempotent, not a work guard
    if (!attr_set) {
        cudaFuncSetAttribute(edge_decoder_mma,
                             cudaFuncAttributeMaxDynamicSharedMemorySize, SMEM_BYTES);
        attr_set = true;
    }

    int sms = 148;
    cudaDeviceGetAttribute(&sms, cudaDevAttrMultiProcessorCount, 0);
    int numTiles = (E + ETILE - 1) / ETILE;
    int grid = 2 * sms;
    if (grid > numTiles) grid = numTiles;

    edge_decoder_mma<<<grid, NT, SMEM_BYTES>>>(zs, zc, row, col, W1, b1, W2, b2, out, E);
}

// round 5
// speedup vs baseline: 4.9742x; 1.0536x over previous
#include <cuda_runtime.h>
#include <cstdint>

#define NT     128
#define ETILE  32
#define KDIM   256
#define HID    128
#define SROW   528                     // bytes per edge-row (256 fp16 + 16B pad)
#define ZBUF   (ETILE * SROW)          // 16896 B per buffer
#define OFF_PRT 0                      // 32 edges * 4 ngroups * 4B = 512
#define OFF_Z   512
#define SMEM_BYTES (OFF_Z + 2 * ZBUF)  // 34304 B -> 2 CTAs/SM

// ---------------- helpers ----------------
__device__ __forceinline__ uint32_t smem_u32(const void* p) {
    uint32_t a;
    asm("{ .reg .u64 t; cvta.to.shared.u64 t, %1; cvt.u32.u64 %0, t; }" : "=r"(a) : "l"(p));
    return a;
}
// pack (lo, hi) floats into f16x2 register, lo in bits[0:16]
__device__ __forceinline__ uint32_t hfpair(float lo, float hi) {
    uint32_t r;
    asm("cvt.rn.f16x2.f32 %0, %1, %2;" : "=r"(r) : "f"(hi), "f"(lo));
    return r;
}
__device__ __forceinline__ void ldmat4(uint32_t (&r)[4], uint32_t addr) {
    asm volatile("ldmatrix.sync.aligned.m8n8.x4.shared.b16 {%0,%1,%2,%3}, [%4];"
                 : "=r"(r[0]), "=r"(r[1]), "=r"(r[2]), "=r"(r[3]) : "r"(addr));
}
__device__ __forceinline__ void mma16816(float (&d)[4], const uint32_t (&a)[4],
                                         uint32_t b0, uint32_t b1) {
    asm volatile("mma.sync.aligned.m16n8k16.row.col.f32.f16.f16.f32 "
                 "{%0,%1,%2,%3}, {%4,%5,%6,%7}, {%8,%9}, {%0,%1,%2,%3};"
                 : "+f"(d[0]), "+f"(d[1]), "+f"(d[2]), "+f"(d[3])
                 : "r"(a[0]), "r"(a[1]), "r"(a[2]), "r"(a[3]), "r"(b0), "r"(b1));
}

// ---------------- gather: gmem load + fp16 convert (regs) ----------------
// 128 threads, 32 edges: e = tid>>2, seg = tid&3 covers 64 floats.
__device__ __forceinline__ void pref_load(const float* __restrict__ zs,
                                          const float* __restrict__ zc,
                                          const int* __restrict__ row,
                                          const int* __restrict__ col,
                                          int base, int E, int tid, uint32_t (&h)[32]) {
    const int e = tid >> 2, seg = tid & 3;
    const int eg = base + e;
    const float* src;
    if (seg < 2) {
        int idx = (eg < E) ? row[eg] : 0;
        src = zs + (size_t)idx * HID + seg * 64;
    } else {
        int idx = (eg < E) ? col[eg] : 0;
        src = zc + (size_t)idx * HID + (seg - 2) * 64;
    }
    #pragma unroll
    for (int j = 0; j < 16; j++) {
        float4 v = ((const float4*)src)[j];
        h[2 * j]     = hfpair(v.x, v.y);
        h[2 * j + 1] = hfpair(v.z, v.w);
    }
}
__device__ __forceinline__ void pref_store(char* zbuf, int tid, const uint32_t (&h)[32]) {
    const int e = tid >> 2, seg = tid & 3;
    char* hb = zbuf + e * SROW + seg * 128;   // 64 halfs = 128B per thread
    #pragma unroll
    for (int i = 0; i < 8; i++)
        *(uint4*)(hb + i * 16) = make_uint4(h[4*i], h[4*i+1], h[4*i+2], h[4*i+3]);
}

// ---------------- kernel ----------------
__global__ void __launch_bounds__(NT, 2)
edge_decoder_mma(const float* __restrict__ zs, const float* __restrict__ zc,
                 const int* __restrict__ row, const int* __restrict__ col,
                 const float* __restrict__ W1, const float* __restrict__ b1,
                 const float* __restrict__ W2, const float* __restrict__ b2,
                 float* __restrict__ out, int E)
{
    extern __shared__ __align__(16) char sm[];
    float* prt = (float*)(sm + OFF_PRT);   // [32 edges][4 ngroups]
    char*  zsm = sm + OFF_Z;

    const int tid  = threadIdx.x;
    const int lane = tid & 31;
    const int wid  = tid >> 5;    // ngroup 0..3
    const int tq   = lane & 3;    // quad -> column pair within n8
    const int tr   = lane >> 2;   // row within m16 / col within n8
    const int wcol = wid * 32;    // this warp's 32 output columns

    // ---- B = W1 fragments, fp16, register-resident (nb=4 -> 128 regs) ----
    // b0 covers k = s*16 + 2*tq (+1); b1 covers k+8. n = wcol + nb*8 + tr.
    uint32_t B[4][16][2];
    #pragma unroll
    for (int nb = 0; nb < 4; nb++) {
        const int n = wcol + nb * 8 + tr;
        #pragma unroll
        for (int s = 0; s < 16; s++) {
            #pragma unroll
            for (int hh = 0; hh < 2; hh++) {
                const int k0 = s * 16 + tq * 2 + hh * 8;
                B[nb][s][hh] = hfpair(W1[(size_t)k0 * HID + n],
                                      W1[(size_t)(k0 + 1) * HID + n]);
            }
        }
    }

    // ---- epilogue constants: this thread's 8 columns (nb,j) ----
    float b1v[4][2], w2v[4][2];
    #pragma unroll
    for (int nb = 0; nb < 4; nb++)
        #pragma unroll
        for (int j = 0; j < 2; j++) {
            int c = wcol + nb * 8 + tq * 2 + j;
            b1v[nb][j] = b1[c];
            w2v[nb][j] = W2[c];
        }
    const float b2v = b2[0];

    const uint32_t zb0 = smem_u32(zsm);
    const uint32_t lanebase = (uint32_t)(lane & 15) * SROW + (uint32_t)(lane >> 4) * 16;

    const int numTiles = (E + ETILE - 1) / ETILE;
    int t = blockIdx.x;
    int buf = 0;
    uint32_t pv[32];

    if (t < numTiles) {
        pref_load(zs, zc, row, col, t * ETILE, E, tid, pv);
        pref_store(zsm, tid, pv);
    }

    while (t < numTiles) {
        const int tn = t + gridDim.x;
        __syncthreads();   // buf visible; prt free

        // issue next tile's gmem loads now -> latency hidden under MMA
        if (tn < numTiles) pref_load(zs, zc, row, col, tn * ETILE, E, tid, pv);

        // ---- MMA mainloop, fp16 single pass; each ldsm.x4 feeds 4 MMAs ----
        float D[2][4][4];
        #pragma unroll
        for (int mb = 0; mb < 2; mb++)
            #pragma unroll
            for (int nb = 0; nb < 4; nb++)
                #pragma unroll
                for (int i = 0; i < 4; i++) D[mb][nb][i] = 0.f;

        const uint32_t zb = zb0 + (uint32_t)buf * ZBUF;
        #pragma unroll
        for (int s = 0; s < 16; s++) {
            uint32_t A[2][4];
            #pragma unroll
            for (int mb = 0; mb < 2; mb++)
                ldmat4(A[mb], zb + lanebase + (uint32_t)mb * (16 * SROW) + (uint32_t)s * 32);
            #pragma unroll
            for (int mb = 0; mb < 2; mb++)
                #pragma unroll
                for (int nb = 0; nb < 4; nb++)
                    mma16816(D[mb][nb], A[mb], B[nb][s][0], B[nb][s][1]);
        }

        // convert + store next tile into other buffer
        if (tn < numTiles) pref_store(zsm + (buf ^ 1) * ZBUF, tid, pv);

        // ---- epilogue: bias + ReLU + W2, reduce over this warp's 32 cols ----
        #pragma unroll
        for (int mb = 0; mb < 2; mb++) {
            float s0 = 0.f, s1 = 0.f;
            #pragma unroll
            for (int nb = 0; nb < 4; nb++) {
                s0 += fmaxf(D[mb][nb][0] + b1v[nb][0], 0.f) * w2v[nb][0];
                s0 += fmaxf(D[mb][nb][1] + b1v[nb][1], 0.f) * w2v[nb][1];
                s1 += fmaxf(D[mb][nb][2] + b1v[nb][0], 0.f) * w2v[nb][0];
                s1 += fmaxf(D[mb][nb][3] + b1v[nb][1], 0.f) * w2v[nb][1];
            }
            s0 += __shfl_xor_sync(0xffffffffu, s0, 1);
            s0 += __shfl_xor_sync(0xffffffffu, s0, 2);
            s1 += __shfl_xor_sync(0xffffffffu, s1, 1);
            s1 += __shfl_xor_sync(0xffffffffu, s1, 2);
            if (tq == 0) {
                prt[(mb * 16 + tr) * 4 + wid]     = s0;   // edge = mb*16 + tr
                prt[(mb * 16 + tr + 8) * 4 + wid] = s1;   // edge = mb*16 + tr + 8
            }
        }
        __syncthreads();
        if (tid < ETILE) {
            float4 p = ((const float4*)prt)[tid];
            float o = p.x + p.y + p.z + p.w + b2v;
            int eg = t * ETILE + tid;
            if (eg < E) out[eg] = o;
        }

        t = tn;
        buf ^= 1;
    }
}

extern "C" void kernel_launch(void* const* d_in, const int* in_sizes, int n_in,
                              void* d_out, int out_size)
{
    const float* zs  = (const float*)d_in[0];
    const float* zc  = (const float*)d_in[1];
    const int*   row = (const int*)d_in[2];
    const int*   col = (const int*)d_in[3];
    const float* W1  = (const float*)d_in[4];
    const float* b1  = (const float*)d_in[5];
    const float* W2  = (const float*)d_in[6];
    const float* b2  = (const float*)d_in[7];
    float* out = (float*)d_out;
    const int E = in_sizes[2];

    static bool attr_set = false;  // idempotent, not a work guard
    if (!attr_set) {
        cudaFuncSetAttribute(edge_decoder_mma,
                             cudaFuncAttributeMaxDynamicSharedMemorySize, SMEM_BYTES);
        attr_set = true;
    }

    int sms = 148;
    cudaDeviceGetAttribute(&sms, cudaDevAttrMultiProcessorCount, 0);
    int numTiles = (E + ETILE - 1) / ETILE;
    int grid = 2 * sms;
    if (grid > numTiles) grid = numTiles;

    edge_decoder_mma<<<grid, NT, SMEM_BYTES>>>(zs, zc, row, col, W1, b1, W2, b2, out, E);
}